// round 7
// baseline (speedup 1.0000x reference)
#include <cuda_runtime.h>
#include <cstdint>

#define Bv 4
#define Sv 4096
#define Hv 32
#define Dv 64
#define NSTEPS 128
#define ROWSTRIDE (Hv * Dv)       // 2048 floats between consecutive s
#define TILE 128                  // rows per tile (4 per warp)
#define NTILES (Sv / TILE)        // 32
#define TILE_FLOATS (TILE * Dv)   // 8192 floats = 32 KB
#define NBUF 3                    // == parity count for s_ag
#define FULL 0xffffffffu
#define PADP 35

// sum across the 8 lanes of a row-group (lanes g*8..g*8+7)
__device__ __forceinline__ float grp8_sum(float v) {
    v += __shfl_xor_sync(FULL, v, 4);
    v += __shfl_xor_sync(FULL, v, 2);
    v += __shfl_xor_sync(FULL, v, 1);
    return v;
}

// inclusive scan across the 4 row-groups (stride-8 lanes)
__device__ __forceinline__ float scan_grp(float v, int lane) {
    float t = __shfl_up_sync(FULL, v, 8);
    if (lane >= 8) v += t;
    t = __shfl_up_sync(FULL, v, 16);
    if (lane >= 16) v += t;
    return v;
}

__device__ __forceinline__ float4 relu4(float4 a) {
    return make_float4(fmaxf(a.x, 0.f), fmaxf(a.y, 0.f),
                       fmaxf(a.z, 0.f), fmaxf(a.w, 0.f));
}
__device__ __forceinline__ float dot4(float4 a, float4 b) {
    return fmaf(a.x, b.x, fmaf(a.y, b.y, fmaf(a.z, b.z, a.w * b.w)));
}

__device__ __forceinline__ void cp16(float* dst_smem, const float* src) {
    uint32_t d = (uint32_t)__cvta_generic_to_shared(dst_smem);
    asm volatile("cp.async.cg.shared.global [%0], [%1], 16;"
                 :: "r"(d), "l"(src) : "memory");
}

__global__ __launch_bounds__(1024, 1)
void rope_ctx_kernel(const float* __restrict__ q,
                     const float* __restrict__ k,
                     const float* __restrict__ cos_step,
                     const float* __restrict__ sin_step,
                     float* __restrict__ out)
{
    extern __shared__ float smem[];
    float* sk = smem;                         // [NBUF][TILE][64]
    float* sq = smem + NBUF * TILE_FLOATS;    // [NBUF][TILE][64]

    __shared__ float2 s_tab[NSTEPS];
    // one parity per in-flight tile stage; scan is done in-place (shifted)
    __shared__ float  s_ag[NBUF][64][PADP];

    const int tid  = threadIdx.x;
    const int w    = tid >> 5;
    const int lane = tid & 31;
    const int g    = lane >> 3;               // row group 0..3
    const int j    = lane & 7;                // dim slot within row
    const int b    = blockIdx.x >> 5;         // H = 32
    const int h    = blockIdx.x & 31;

    if (tid < NSTEPS) {
        s_tab[tid] = make_float2(cos_step[tid * Dv], sin_step[tid * Dv]);
    }

    const size_t base = (size_t)b * Sv * ROWSTRIDE + (size_t)h * Dv;
    const float* qg = q + base;
    const float* kg = k + base;
    float* og = out + base;
    const size_t KOUT = (size_t)Bv * Sv * ROWSTRIDE;

    const int dx = 4 * j;              // x dims: dx..dx+3 ; y dims: 32+dx..
    const int dy = 32 + 4 * j;
    const int r  = (w << 2) + g;       // this thread's row within a tile
    const int sodx = (r << 6) + dx;    // thread's smem offsets
    const int sody = (r << 6) + dy;

    // per-thread-exact staging: a thread copies ONLY the words it will read,
    // so cp.async.wait_group alone makes them visible to it (no barrier).
    auto issue = [&](int t) {
        if (t < NTILES) {
            const int p = t % NBUF;
            float* skb = sk + p * TILE_FLOATS;
            float* sqb = sq + p * TILE_FLOATS;
            const size_t go = (size_t)(t * TILE + r) * ROWSTRIDE;
            cp16(skb + sodx, kg + go + dx);
            cp16(skb + sody, kg + go + dy);
            cp16(sqb + sodx, qg + go + dx);
            cp16(sqb + sody, qg + go + dy);
        }
        asm volatile("cp.async.commit_group;" ::: "memory");
    };

    float4 basex = make_float4(0.f, 0.f, 0.f, 0.f);
    float4 basey = make_float4(0.f, 0.f, 0.f, 0.f);

    // pipelined per-thread state
    float4 ix, iy, qrx, qry;
    float  qinv, cn, sn;

    // A: load tile (smem->reg), k norm+scan, publish aggregates, q norm
    auto phaseA = [&](int p) {
        const float* skb = sk + p * TILE_FLOATS;
        const float* sqb = sq + p * TILE_FLOATS;
        float4 kx = *(const float4*)(skb + sodx);
        float4 ky = *(const float4*)(skb + sody);
        float4 qx = *(const float4*)(sqb + sodx);
        float4 qy = *(const float4*)(sqb + sody);

        float4 knx = relu4(kx), kny = relu4(ky);
        float ss = grp8_sum(dot4(knx, knx) + dot4(kny, kny));
        float kinv = __fdividef(1.f, sqrtf(ss) + 1e-6f);
        knx.x *= kinv; knx.y *= kinv; knx.z *= kinv; knx.w *= kinv;
        kny.x *= kinv; kny.y *= kinv; kny.z *= kinv; kny.w *= kinv;

        ix.x = scan_grp(knx.x, lane); ix.y = scan_grp(knx.y, lane);
        ix.z = scan_grp(knx.z, lane); ix.w = scan_grp(knx.w, lane);
        iy.x = scan_grp(kny.x, lane); iy.y = scan_grp(kny.y, lane);
        iy.z = scan_grp(kny.z, lane); iy.w = scan_grp(kny.w, lane);

        if (g == 3) {                  // group 3 holds the warp's 4-row totals
            s_ag[p][dx    ][w] = ix.x; s_ag[p][dx + 1][w] = ix.y;
            s_ag[p][dx + 2][w] = ix.z; s_ag[p][dx + 3][w] = ix.w;
            s_ag[p][dy    ][w] = iy.x; s_ag[p][dy + 1][w] = iy.y;
            s_ag[p][dy + 2][w] = iy.z; s_ag[p][dy + 3][w] = iy.w;
        }

        qrx = relu4(qx); qry = relu4(qy);
        float qs = grp8_sum(dot4(qrx, qrx) + dot4(qry, qry));
        qinv = __fdividef(1.f, sqrtf(qs) + 1e-6f);
    };

    // C: in-place cross-warp scan (warp w owns dims 2w,2w+1), shifted write
    auto phaseC = [&](int p) {
        #pragma unroll
        for (int dd = 0; dd < 2; ++dd) {
            const int d = 2 * w + dd;
            float v = s_ag[p][d][lane];
            float u;
            u = __shfl_up_sync(FULL, v, 1);  if (lane >= 1)  v += u;
            u = __shfl_up_sync(FULL, v, 2);  if (lane >= 2)  v += u;
            u = __shfl_up_sync(FULL, v, 4);  if (lane >= 4)  v += u;
            u = __shfl_up_sync(FULL, v, 8);  if (lane >= 8)  v += u;
            u = __shfl_up_sync(FULL, v, 16); if (lane >= 16) v += u;
            s_ag[p][d][lane + 1] = v;       // exclusive at [w], total at [32]
            if (lane == 0) s_ag[p][d][0] = 0.f;
        }
    };

    // S: rope + store tile t using cn/sn from D(t); reloads k,q from buffer
    auto phaseS = [&](int t, int p) {
        const float* skb = sk + p * TILE_FLOATS;
        const float* sqb = sq + p * TILE_FLOATS;
        float4 kx = *(const float4*)(skb + sodx);
        float4 ky = *(const float4*)(skb + sody);
        float4 qx = *(const float4*)(sqb + sodx);
        float4 qy = *(const float4*)(sqb + sody);

        float4 oqx, oqy, okx, oky;
        oqx.x = fmaf(qx.x, cn, -qy.x * sn);  oqy.x = fmaf(qy.x, cn, qx.x * sn);
        oqx.y = fmaf(qx.y, cn, -qy.y * sn);  oqy.y = fmaf(qy.y, cn, qx.y * sn);
        oqx.z = fmaf(qx.z, cn, -qy.z * sn);  oqy.z = fmaf(qy.z, cn, qx.z * sn);
        oqx.w = fmaf(qx.w, cn, -qy.w * sn);  oqy.w = fmaf(qy.w, cn, qx.w * sn);
        okx.x = fmaf(kx.x, cn, -ky.x * sn);  oky.x = fmaf(ky.x, cn, kx.x * sn);
        okx.y = fmaf(kx.y, cn, -ky.y * sn);  oky.y = fmaf(ky.y, cn, kx.y * sn);
        okx.z = fmaf(kx.z, cn, -ky.z * sn);  oky.z = fmaf(ky.z, cn, kx.z * sn);
        okx.w = fmaf(kx.w, cn, -ky.w * sn);  oky.w = fmaf(ky.w, cn, kx.w * sn);

        const size_t ro = (size_t)(t * TILE + r) * ROWSTRIDE + dx;
        *(float4*)(og + ro)             = oqx;
        *(float4*)(og + ro + 32)        = oqy;
        *(float4*)(og + KOUT + ro)      = okx;
        *(float4*)(og + KOUT + ro + 32) = oky;
    };

    // D: assemble cum, dot, position, table lerp -> cn, sn (short chain)
    auto phaseD = [&](int p) {
        float4 cx, cy;
        cx.x = basex.x + s_ag[p][dx    ][w] + ix.x;
        cx.y = basex.y + s_ag[p][dx + 1][w] + ix.y;
        cx.z = basex.z + s_ag[p][dx + 2][w] + ix.z;
        cx.w = basex.w + s_ag[p][dx + 3][w] + ix.w;
        cy.x = basey.x + s_ag[p][dy    ][w] + iy.x;
        cy.y = basey.y + s_ag[p][dy + 1][w] + iy.y;
        cy.z = basey.z + s_ag[p][dy + 2][w] + iy.z;
        cy.w = basey.w + s_ag[p][dy + 3][w] + iy.w;

        basex.x += s_ag[p][dx    ][32]; basex.y += s_ag[p][dx + 1][32];
        basex.z += s_ag[p][dx + 2][32]; basex.w += s_ag[p][dx + 3][32];
        basey.x += s_ag[p][dy    ][32]; basey.y += s_ag[p][dy + 1][32];
        basey.z += s_ag[p][dy + 2][32]; basey.w += s_ag[p][dy + 3][32];

        float dot = grp8_sum(dot4(qrx, cx) + dot4(qry, cy)) * qinv;

        float pp = fminf(fmaxf(dot * (1.f / 32.f), 0.f), 127.f);
        float pf = floorf(pp);
        int   fi = (int)pf;
        int   ci = (int)ceilf(pp);
        float fr = pp - pf;
        float2 t0 = s_tab[fi], t1 = s_tab[ci];
        cn = fmaf(fr, t1.x - t0.x, t0.x);
        sn = fmaf(fr, t1.y - t0.y, t0.y);
    };

    // ---- prologue: tile 0 (no S yet) ---------------------------------------
    issue(0);
    issue(1);
    asm volatile("cp.async.wait_group 1;" ::: "memory");
    phaseA(0);
    __syncthreads();                   // B1
    phaseC(0);
    issue(2);
    __syncthreads();                   // B2
    phaseD(0);

    // ---- steady state: S(t-1) fills the scan bubble ------------------------
    for (int t = 1; t < NTILES; ++t) {
        const int p  = t % NBUF;       // parity/buffer of tile t
        const int pm = (t - 1) % NBUF; // parity/buffer of tile t-1 (still live)

        asm volatile("cp.async.wait_group 1;" ::: "memory");
        phaseA(p);
        __syncthreads();               // B1: s_ag[p] published

        phaseS(t - 1, pm);             // independent of C; fills the bubble
        phaseC(p);
        issue(t + 2);                  // overwrites buf pm AFTER S's reads (WAR ok)
        __syncthreads();               // B2: s_ag[p] scanned

        phaseD(p);
    }

    // ---- epilogue -----------------------------------------------------------
    phaseS(NTILES - 1, (NTILES - 1) % NBUF);
}

extern "C" void kernel_launch(void* const* d_in, const int* in_sizes, int n_in,
                              void* d_out, int out_size)
{
    const float* q        = (const float*)d_in[0];
    const float* k        = (const float*)d_in[1];
    // d_in[2] = v (unused by the reference math)
    const float* cos_step = (const float*)d_in[3];
    const float* sin_step = (const float*)d_in[4];
    // d_in[5] = offset (unused by the reference math)

    const size_t dyn = (size_t)2 * NBUF * TILE_FLOATS * sizeof(float); // 192 KB
    cudaFuncSetAttribute(rope_ctx_kernel,
                         cudaFuncAttributeMaxDynamicSharedMemorySize, (int)dyn);
    rope_ctx_kernel<<<Bv * Hv, 1024, dyn>>>(q, k, cos_step, sin_step,
                                            (float*)d_out);
}